// round 8
// baseline (speedup 1.0000x reference)
#include <cuda_runtime.h>
#include <cuda_bf16.h>
#include <math.h>
#include <stdint.h>

#define BB   32768
#define FF   256
#define HH   128
#define OUTD 64
#define NSTG 26
#define SQH  0.70710678118654752f

// ---------------- device scratch ----------------
__device__ float g_xbn[BB * FF];            // fp32 BN(x) (masked product precision)
__device__ float g_compl[BB * FF];
__device__ __nv_bfloat16 g_Y[BB * FF];      // GEMM output bf16
__device__ float g_h[2][BB * HH];           // fp32 residual ping-pong
__device__ __nv_bfloat16 g_xb[BB * FF];     // bf16 BN(x) (GEMM A, step 0)
__device__ __nv_bfloat16 g_Wt[507904];      // transposed weights [N=256, K]
__device__ float g_sum[NSTG * 256];
__device__ float g_sumsq[NSTG * 256];

// ---------------- helpers ----------------
__device__ __forceinline__ uint32_t smem_u32(const void* p) {
    return (uint32_t)__cvta_generic_to_shared(p);
}
__device__ __forceinline__ void ldsm4(uint32_t* r, const void* p) {
    asm volatile("ldmatrix.sync.aligned.m8n8.x4.shared.b16 {%0,%1,%2,%3}, [%4];"
                 : "=r"(r[0]), "=r"(r[1]), "=r"(r[2]), "=r"(r[3]) : "r"(smem_u32(p)));
}
__device__ __forceinline__ void mma16816(float* c, const uint32_t* a, const uint32_t* b) {
    asm volatile(
        "mma.sync.aligned.m16n8k16.row.col.f32.bf16.bf16.f32 "
        "{%0,%1,%2,%3}, {%4,%5,%6,%7}, {%8,%9}, {%0,%1,%2,%3};"
        : "+f"(c[0]), "+f"(c[1]), "+f"(c[2]), "+f"(c[3])
        : "r"(a[0]), "r"(a[1]), "r"(a[2]), "r"(a[3]), "r"(b[0]), "r"(b[1]));
}
__device__ __forceinline__ void cpasync16(uint32_t dst, const void* src) {
    asm volatile("cp.async.ca.shared.global [%0], [%1], 16;" :: "r"(dst), "l"(src));
}
__device__ __forceinline__ void cpcommit() { asm volatile("cp.async.commit_group;"); }

// ---------------- stats zero ----------------
__global__ void zero_stats_k() {
    int i = blockIdx.x * 256 + threadIdx.x;
    g_sum[i] = 0.f; g_sumsq[i] = 0.f;
}

// ---------------- W transpose -> bf16 [N=256,K] ----------------
__global__ void convw_k(const float* __restrict__ W1, const float* __restrict__ W2,
                        const float* __restrict__ W3, const float* __restrict__ W4,
                        const float* __restrict__ Wc) {
    int idx = blockIdx.x * 256 + threadIdx.x;   // < 507904
    const float* src; int base, K;
    if (idx < 65536)       { src = W1; base = 0; K = 256; }
    else if (idx < 98304)  { src = W2; base = 65536; K = 128; }
    else if (idx < 262144) { int m = (idx - 98304) >> 15; src = W3 + m * HH * FF; base = 98304 + (m << 15); K = 128; }
    else if (idx < 425984) { int m = (idx - 262144) >> 15; src = W4 + m * HH * FF; base = 262144 + (m << 15); K = 128; }
    else                   { int m = (idx - 425984) >> 14; src = Wc + m * OUTD * FF; base = 425984 + (m << 14); K = 64; }
    int local = idx - base;
    int n = local / K, k = local - n * K;
    g_Wt[idx] = __float2bfloat16(src[k * 256 + n]);
}

// ---------------- column stats for x ----------------
__global__ void colstats_k(const float* __restrict__ X) {
    int col = threadIdx.x;
    int r0  = blockIdx.x * 128;
    float s = 0.f, s2 = 0.f;
#pragma unroll 8
    for (int r = 0; r < 128; r++) {
        float v = X[(r0 + r) * 256 + col];
        s += v; s2 += v * v;
    }
    atomicAdd(&g_sum[col], s);
    atomicAdd(&g_sumsq[col], s2);
}

// ---------------- input BN apply + trivial output ----------
__global__ void apply_x_k(const float* __restrict__ x, const float* __restrict__ eg,
                          const float* __restrict__ eb, float* __restrict__ out, int out_size) {
    int idx4 = blockIdx.x * 256 + threadIdx.x;     // BB*FF/4 threads
    int col4 = (idx4 & 63) * 4, row = idx4 >> 6;
    float4 xv = *(const float4*)(x + (size_t)idx4 * 4);
    float v[4];
#pragma unroll
    for (int i = 0; i < 4; i++) {
        int col = col4 + i;
        float mean = g_sum[col] * (1.f / BB);
        float var  = g_sumsq[col] * (1.f / BB) - mean * mean;
        float a = eg[col] * rsqrtf(var + 1e-5f);
        float c = eb[col] - mean * a;
        v[i] = ((const float*)&xv)[i] * a + c;
    }
    *(float4*)(g_xbn + (size_t)idx4 * 4)   = make_float4(v[0], v[1], v[2], v[3]);
    *(float4*)(g_compl + (size_t)idx4 * 4) = make_float4(1.f, 1.f, 1.f, 1.f);
    __nv_bfloat162 p0 = {__float2bfloat16(v[0]), __float2bfloat16(v[1])};
    __nv_bfloat162 p1 = {__float2bfloat16(v[2]), __float2bfloat16(v[3])};
    *(__nv_bfloat162*)(g_xb + (size_t)idx4 * 4)     = p0;
    *(__nv_bfloat162*)(g_xb + (size_t)idx4 * 4 + 2) = p1;
    if (col4 < OUTD) {
        float4 o = make_float4(5.f * fmaxf(v[0], 0.f), 5.f * fmaxf(v[1], 0.f),
                               5.f * fmaxf(v[2], 0.f), 5.f * fmaxf(v[3], 0.f));
        *(float4*)(out + (size_t)row * OUTD + col4) = o;
    }
    if (idx4 == 0) for (int i = BB * OUTD; i < out_size; i++) out[i] = 0.0f;
}

// ============================================================================
// Fused kernel: [activation/softmax prologue -> smem A] + bf16 HMMA GEMM
// Tile: 128 rows x 256 cols per CTA (grid 256). Epilogue: Y bf16 + fp32 stats.
// mode: 0 = A copy from g_xb (K=256)
//       1 = softmax/entropy/mask prologue, A = masked (K=256)
//       2 = GLU (no residual), writes g_h[hw], A = h (K=128)
//       3 = GLU + residual g_h[hr], writes g_h[hw], A = h (K=128)
//       4 = GLU + residual g_h[hr], cols 64..127 only, A = fc (K=64)
// ============================================================================
__global__ __launch_bounds__(256, 1) void fused_k(
    int mode, int K, int Woff, int st, int stPrev,
    const float* __restrict__ gPrev, const float* __restrict__ bPrev,
    int hr, int hw, float* __restrict__ ent_out)
{
    extern __shared__ char smem[];
    __nv_bfloat16* sA = (__nv_bfloat16*)smem;
    __nv_bfloat16* sB = (__nv_bfloat16*)(smem + 67584);

    const int tid = threadIdx.x, wid = tid >> 5, lane = tid & 31;
    const int row0 = blockIdx.x * 128;
    const int astr = K + 8;

    const float* SP = g_sum   + stPrev * 256;
    const float* QP = g_sumsq + stPrev * 256;

    // ---------------- prologue: build smem A tile ----------------
    if (mode == 0) {
        for (int v = tid; v < 128 * 32; v += 256) {
            int r = v >> 5, c8 = (v & 31) * 8;
            *(uint4*)&sA[r * 264 + c8] = *(const uint4*)(g_xb + (size_t)(row0 + r) * 256 + c8);
        }
    } else if (mode == 1) {
        // warp-per-row softmax over 256 features; 16 rows per warp
        float a_arr[8], c_arr[8];
#pragma unroll
        for (int k = 0; k < 8; k++) {
            int col = lane + 32 * k;
            float mean = SP[col] * (1.f / BB);
            float var  = QP[col] * (1.f / BB) - mean * mean;
            float a = gPrev[col] * rsqrtf(var + 1e-5f);
            a_arr[k] = a;
            c_arr[k] = bPrev[col] - mean * a;
        }
        float entw = 0.f;
        for (int i = 0; i < 16; i++) {
            int row = row0 + wid * 16 + i;
            int base = row * 256;
            float t[8], cm[8];
            float mx = -1e30f;
#pragma unroll
            for (int k = 0; k < 8; k++) {
                int col = lane + 32 * k;
                cm[k] = g_compl[base + col];
                t[k]  = (__bfloat162float(g_Y[base + col]) * a_arr[k] + c_arr[k]) * cm[k];
                mx = fmaxf(mx, t[k]);
            }
#pragma unroll
            for (int o = 16; o; o >>= 1) mx = fmaxf(mx, __shfl_xor_sync(0xffffffffu, mx, o));
            float e[8], ss = 0.f;
#pragma unroll
            for (int k = 0; k < 8; k++) { e[k] = expf(t[k] - mx); ss += e[k]; }
#pragma unroll
            for (int o = 16; o; o >>= 1) ss += __shfl_xor_sync(0xffffffffu, ss, o);
            float inv = 1.0f / ss;
            int rl = wid * 16 + i;
#pragma unroll
            for (int k = 0; k < 8; k++) {
                int col = lane + 32 * k;
                float m = e[k] * inv;
                entw -= m * logf(m + 1e-5f);
                g_compl[base + col] = cm[k] * (1.5f - m);
                sA[rl * 264 + col] = __float2bfloat16(m * g_xbn[base + col]);
            }
        }
#pragma unroll
        for (int o = 16; o; o >>= 1) entw += __shfl_xor_sync(0xffffffffu, entw, o);
        if (lane == 0) atomicAdd(ent_out, entw * (1.0f / (32768.0f * 5.0f)));
    } else if (mode == 2 || mode == 3) {
        for (int idx2 = tid; idx2 < 128 * 64; idx2 += 256) {
            int r = idx2 >> 6, j2 = (idx2 & 63) * 2;
            float h01[2];
            __nv_bfloat162 y1p = *(const __nv_bfloat162*)(g_Y + (size_t)(row0 + r) * 256 + j2);
            __nv_bfloat162 y2p = *(const __nv_bfloat162*)(g_Y + (size_t)(row0 + r) * 256 + 128 + j2);
#pragma unroll
            for (int i = 0; i < 2; i++) {
                int j = j2 + i;
                float m1 = SP[j]       * (1.f / BB), m2 = SP[j + 128] * (1.f / BB);
                float v1 = QP[j]       * (1.f / BB) - m1 * m1;
                float v2 = QP[j + 128] * (1.f / BB) - m2 * m2;
                float a1 = gPrev[j]       * rsqrtf(v1 + 1e-5f);
                float a2 = gPrev[j + 128] * rsqrtf(v2 + 1e-5f);
                float c1 = bPrev[j]       - m1 * a1;
                float c2 = bPrev[j + 128] - m2 * a2;
                float y1 = __bfloat162float((i == 0) ? y1p.x : y1p.y) * a1 + c1;
                float y2 = __bfloat162float((i == 0) ? y2p.x : y2p.y) * a2 + c2;
                h01[i] = y1 / (1.0f + expf(-y2));
            }
            if (mode == 3) {
                float2 hp = *(const float2*)(g_h[hr] + (size_t)(row0 + r) * 128 + j2);
                h01[0] = (h01[0] + hp.x) * SQH;
                h01[1] = (h01[1] + hp.y) * SQH;
            }
            *(float2*)(g_h[hw] + (size_t)(row0 + r) * 128 + j2) = make_float2(h01[0], h01[1]);
            sA[r * 136 + j2]     = __float2bfloat16(h01[0]);
            sA[r * 136 + j2 + 1] = __float2bfloat16(h01[1]);
        }
    } else { // mode 4: fc = h4[:, 64:128]
        for (int idx2 = tid; idx2 < 128 * 32; idx2 += 256) {
            int r = idx2 >> 5, j2 = 64 + (idx2 & 31) * 2;
            float h01[2];
            __nv_bfloat162 y1p = *(const __nv_bfloat162*)(g_Y + (size_t)(row0 + r) * 256 + j2);
            __nv_bfloat162 y2p = *(const __nv_bfloat162*)(g_Y + (size_t)(row0 + r) * 256 + 128 + j2);
#pragma unroll
            for (int i = 0; i < 2; i++) {
                int j = j2 + i;
                float m1 = SP[j]       * (1.f / BB), m2 = SP[j + 128] * (1.f / BB);
                float v1 = QP[j]       * (1.f / BB) - m1 * m1;
                float v2 = QP[j + 128] * (1.f / BB) - m2 * m2;
                float a1 = gPrev[j]       * rsqrtf(v1 + 1e-5f);
                float a2 = gPrev[j + 128] * rsqrtf(v2 + 1e-5f);
                float c1 = bPrev[j]       - m1 * a1;
                float c2 = bPrev[j + 128] - m2 * a2;
                float y1 = __bfloat162float((i == 0) ? y1p.x : y1p.y) * a1 + c1;
                float y2 = __bfloat162float((i == 0) ? y2p.x : y2p.y) * a2 + c2;
                h01[i] = y1 / (1.0f + expf(-y2));
            }
            float2 hp = *(const float2*)(g_h[hr] + (size_t)(row0 + r) * 128 + j2);
            h01[0] = (h01[0] + hp.x) * SQH;
            h01[1] = (h01[1] + hp.y) * SQH;
            sA[r * 72 + (j2 - 64)]     = __float2bfloat16(h01[0]);
            sA[r * 72 + (j2 - 64) + 1] = __float2bfloat16(h01[1]);
        }
    }

    // ---------------- GEMM: Y[row0:row0+128, 0:256] = sA @ W ----------------
    float acc[2][16][4];
#pragma unroll
    for (int i = 0; i < 2; i++)
#pragma unroll
        for (int j = 0; j < 16; j++)
#pragma unroll
            for (int e = 0; e < 4; e++) acc[i][j][e] = 0.f;

    const __nv_bfloat16* W = g_Wt + Woff;
    const int nch = K >> 6;

    const int a_row = (wid & 3) * 32 + (lane & 15);
    const int a_koff = (lane >> 4) << 3;
    const int b_row0 = (wid >> 2) * 128 + (lane & 7) + ((lane & 16) ? 8 : 0);
    const int b_koff = lane & 8;

    // prefetch chunk 0
    {
        const int r = tid >> 3, c8 = (tid & 7) * 8;
#pragma unroll
        for (int t = 0; t < 8; t++) {
            int rr = r + t * 32;
            cpasync16(smem_u32(&sB[rr * 72 + c8]), W + (size_t)rr * K + c8);
        }
        cpcommit();
    }

    for (int c = 0; c < nch; c++) {
        if (c + 1 < nch) {
            const int buf = (c + 1) & 1;
            const int r = tid >> 3, c8 = (tid & 7) * 8;
#pragma unroll
            for (int t = 0; t < 8; t++) {
                int rr = r + t * 32;
                cpasync16(smem_u32(&sB[buf * 256 * 72 + rr * 72 + c8]),
                          W + (size_t)rr * K + (c + 1) * 64 + c8);
            }
            cpcommit();
            asm volatile("cp.async.wait_group 1;");
        } else {
            asm volatile("cp.async.wait_group 0;");
        }
        __syncthreads();

        const __nv_bfloat16* bbuf = &sB[(c & 1) * 256 * 72];
#pragma unroll
        for (int k4 = 0; k4 < 4; k4++) {
            const int kkg = c * 64 + k4 * 16;
            uint32_t ah[2][4];
            ldsm4(ah[0], &sA[a_row * astr + kkg + a_koff]);
            ldsm4(ah[1], &sA[(a_row + 16) * astr + kkg + a_koff]);
#pragma unroll
            for (int nf2 = 0; nf2 < 8; nf2++) {
                uint32_t bh[4];
                ldsm4(bh, &bbuf[(b_row0 + nf2 * 16) * 72 + k4 * 16 + b_koff]);
                mma16816(acc[0][nf2 * 2],     ah[0], &bh[0]);
                mma16816(acc[0][nf2 * 2 + 1], ah[0], &bh[2]);
                mma16816(acc[1][nf2 * 2],     ah[1], &bh[0]);
                mma16816(acc[1][nf2 * 2 + 1], ah[1], &bh[2]);
            }
        }
        __syncthreads();
    }

    // ---------------- epilogue: bf16 Y + fp32 column stats ----------------
    const int g = lane >> 2, tg = lane & 3;
    const int mbase = row0 + (wid & 3) * 32;
    const int nbase = (wid >> 2) * 128;
    float* S = g_sum   + st * 256;
    float* Q = g_sumsq + st * 256;

#pragma unroll
    for (int nf = 0; nf < 16; nf++) {
        int cN = nbase + nf * 8 + tg * 2;
        float s0 = 0.f, s1 = 0.f, q0 = 0.f, q1 = 0.f;
#pragma unroll
        for (int mf = 0; mf < 2; mf++) {
            int r = mbase + mf * 16 + g;
            float e0 = acc[mf][nf][0], e1 = acc[mf][nf][1];
            float e2 = acc[mf][nf][2], e3 = acc[mf][nf][3];
            __nv_bfloat162 p0 = {__float2bfloat16(e0), __float2bfloat16(e1)};
            __nv_bfloat162 p1 = {__float2bfloat16(e2), __float2bfloat16(e3)};
            *(__nv_bfloat162*)(g_Y + (size_t)r * 256 + cN)       = p0;
            *(__nv_bfloat162*)(g_Y + (size_t)(r + 8) * 256 + cN) = p1;
            s0 += e0 + e2; s1 += e1 + e3;
            q0 += e0 * e0 + e2 * e2; q1 += e1 * e1 + e3 * e3;
        }
#pragma unroll
        for (int o = 4; o < 32; o <<= 1) {
            s0 += __shfl_xor_sync(0xffffffffu, s0, o);
            s1 += __shfl_xor_sync(0xffffffffu, s1, o);
            q0 += __shfl_xor_sync(0xffffffffu, q0, o);
            q1 += __shfl_xor_sync(0xffffffffu, q1, o);
        }
        if (lane < 4) {
            atomicAdd(&S[cN], s0);
            atomicAdd(&S[cN + 1], s1);
            atomicAdd(&Q[cN], q0);
            atomicAdd(&Q[cN + 1], q1);
        }
    }
}

// ---------------- final-step entropy (no mask update) ----------------
__global__ void entropy_k(int st, const float* __restrict__ gcv,
                          const float* __restrict__ bcv, float* __restrict__ ent_out) {
    int lane = threadIdx.x & 31, w = threadIdx.x >> 5;
    int row  = blockIdx.x * 8 + w;
    int base = row * 256;
    const float* S = g_sum   + st * 256;
    const float* Q = g_sumsq + st * 256;

    float t[8];
    float mx = -1e30f;
#pragma unroll
    for (int k = 0; k < 8; k++) {
        int col = lane + 32 * k;
        float mean = S[col] * (1.f / BB);
        float var  = Q[col] * (1.f / BB) - mean * mean;
        float a = gcv[col] * rsqrtf(var + 1e-5f);
        float c = bcv[col] - mean * a;
        t[k] = (__bfloat162float(g_Y[base + col]) * a + c) * g_compl[base + col];
        mx = fmaxf(mx, t[k]);
    }
#pragma unroll
    for (int o = 16; o; o >>= 1) mx = fmaxf(mx, __shfl_xor_sync(0xffffffffu, mx, o));
    float e[8], ss = 0.f;
#pragma unroll
    for (int k = 0; k < 8; k++) { e[k] = expf(t[k] - mx); ss += e[k]; }
#pragma unroll
    for (int o = 16; o; o >>= 1) ss += __shfl_xor_sync(0xffffffffu, ss, o);
    float inv = 1.0f / ss;
    float ent = 0.f;
#pragma unroll
    for (int k = 0; k < 8; k++) {
        float m = e[k] * inv;
        ent -= m * logf(m + 1e-5f);
    }
#pragma unroll
    for (int o = 16; o; o >>= 1) ent += __shfl_xor_sync(0xffffffffu, ent, o);
    if (lane == 0) atomicAdd(ent_out, ent * (1.0f / (32768.0f * 5.0f)));
}

// ---------------- launcher ----------------
extern "C" void kernel_launch(void* const* d_in, const int* in_sizes, int n_in,
                              void* d_out, int out_size) {
    (void)in_sizes; (void)n_in;
    const float* x     = (const float*)d_in[0];
    const float* enc_g = (const float*)d_in[1];
    const float* enc_b = (const float*)d_in[2];
    const float* W1    = (const float*)d_in[3];
    const float* g1    = (const float*)d_in[4];
    const float* b1    = (const float*)d_in[5];
    const float* W2    = (const float*)d_in[6];
    const float* g2    = (const float*)d_in[7];
    const float* b2    = (const float*)d_in[8];
    const float* W3    = (const float*)d_in[9];
    const float* g3    = (const float*)d_in[10];
    const float* b3    = (const float*)d_in[11];
    const float* W4    = (const float*)d_in[12];
    const float* g4    = (const float*)d_in[13];
    const float* b4    = (const float*)d_in[14];
    const float* Wc    = (const float*)d_in[15];
    const float* gc    = (const float*)d_in[16];
    const float* bc    = (const float*)d_in[17];

    float* out = (float*)d_out;
    float* ent = out + (out_size - 1);

    const int SMEMSZ = 67584 + 2 * 256 * 72 * 2;   // 141312
    static int smem_set = 0;
    if (!smem_set) {
        cudaFuncSetAttribute(fused_k, cudaFuncAttributeMaxDynamicSharedMemorySize, SMEMSZ);
        smem_set = 1;
    }

    // setup
    zero_stats_k<<<NSTG, 256>>>();
    convw_k<<<1984, 256>>>(W1, W2, W3, W4, Wc);
    colstats_k<<<256, 256>>>(x);
    apply_x_k<<<BB * FF / 1024, 256>>>(x, enc_g, enc_b, out, out_size);

    // steps 0..4 (step 5 dead code: out depends only on BN(x))
    for (int ni = 0; ni < 5; ni++) {
        int st1 = 1 + ni * 5;
        int st2 = st1 + 1, st3 = st1 + 2, st4 = st1 + 3, stc = st1 + 4;
        int stcPrev = st1 - 1;   // stc of previous step (ni>0)

        // G1: A = masked (or xb on step 0), K=256
        if (ni == 0)
            fused_k<<<256, 256, SMEMSZ>>>(0, 256, 0, st1, 0, nullptr, nullptr, -1, -1, ent);
        else
            fused_k<<<256, 256, SMEMSZ>>>(1, 256, 0, st1, stcPrev,
                                          gc + (ni - 1) * 256, bc + (ni - 1) * 256, -1, -1, ent);
        // G2: prologue h1 = glu(Y1; st1, g1,b1) -> g_h[0]; A = h1, K=128
        fused_k<<<256, 256, SMEMSZ>>>(2, 128, 65536, st2, st1, g1, b1, -1, 0, ent);
        // G3: prologue h2 = (glu(Y2; st2, g2,b2) + h1)*s -> g_h[1]
        fused_k<<<256, 256, SMEMSZ>>>(3, 128, 98304 + ni * 32768, st3, st2, g2, b2, 0, 1, ent);
        // G4: prologue h3 = (glu(Y3; st3, g3[ni],b3[ni]) + h2)*s -> g_h[0]
        fused_k<<<256, 256, SMEMSZ>>>(3, 128, 262144 + ni * 32768, st4, st3,
                                      g3 + ni * 256, b3 + ni * 256, 1, 0, ent);
        // Gc: prologue fc = ((glu(Y4; st4, g4[ni],b4[ni]) + h3)*s)[:,64:128]; K=64
        fused_k<<<256, 256, SMEMSZ>>>(4, 64, 425984 + ni * 16384, stc, st4,
                                      g4 + ni * 256, b4 + ni * 256, 0, -1, ent);
    }
    // entropy of final step's coef
    entropy_k<<<BB / 8, 256>>>(1 + 4 * 5 + 4, gc + 4 * 256, bc + 4 * 256, ent);
}

// round 9
// speedup vs baseline: 1.4293x; 1.4293x over previous
#include <cuda_runtime.h>
#include <cuda_bf16.h>
#include <math.h>
#include <stdint.h>

#define BB   32768
#define FF   256
#define HH   128
#define OUTD 64
#define NSTG 26
#define BSTR 72    // bf16 elems per smem row: 128B data + 16B pad, conflict-free

// ---------------- device scratch ----------------
__device__ float g_compl[BB * FF];
__device__ __nv_bfloat16 g_Y[BB * FF];            // GEMM output (bf16; stats in fp32)
__device__ float g_h[BB * HH];                    // fp32 residual chain
__device__ __nv_bfloat16 g_xb[BB * FF];           // bf16 BN(x)
__device__ __nv_bfloat16 g_mb[BB * FF];           // bf16 masked
__device__ __nv_bfloat16 g_hb[BB * HH];           // bf16 activation
__device__ __nv_bfloat16 g_Wt[507904];            // transposed weights [N=256, K]
__device__ float g_sum[NSTG * 256];
__device__ float g_sumsq[NSTG * 256];

// ---------------- helpers ----------------
__device__ __forceinline__ uint32_t smem_u32(const void* p) {
    return (uint32_t)__cvta_generic_to_shared(p);
}
__device__ __forceinline__ void ldsm4(uint32_t* r, const void* p) {
    asm volatile("ldmatrix.sync.aligned.m8n8.x4.shared.b16 {%0,%1,%2,%3}, [%4];"
                 : "=r"(r[0]), "=r"(r[1]), "=r"(r[2]), "=r"(r[3]) : "r"(smem_u32(p)));
}
__device__ __forceinline__ void mma16816(float* c, const uint32_t* a, const uint32_t* b) {
    asm volatile(
        "mma.sync.aligned.m16n8k16.row.col.f32.bf16.bf16.f32 "
        "{%0,%1,%2,%3}, {%4,%5,%6,%7}, {%8,%9}, {%0,%1,%2,%3};"
        : "+f"(c[0]), "+f"(c[1]), "+f"(c[2]), "+f"(c[3])
        : "r"(a[0]), "r"(a[1]), "r"(a[2]), "r"(a[3]), "r"(b[0]), "r"(b[1]));
}
__device__ __forceinline__ void cpasync16(uint32_t dst, const void* src) {
    asm volatile("cp.async.ca.shared.global [%0], [%1], 16;" :: "r"(dst), "l"(src));
}

// ---------------- stats zero ----------------
__global__ void zero_stats_k() {
    int i = blockIdx.x * 256 + threadIdx.x;
    g_sum[i] = 0.f; g_sumsq[i] = 0.f;
}

// ---------------- W transpose -> bf16 [N=256,K] ----------------
__global__ void convw_k(const float* __restrict__ W1, const float* __restrict__ W2,
                        const float* __restrict__ W3, const float* __restrict__ W4,
                        const float* __restrict__ Wc) {
    int idx = blockIdx.x * 256 + threadIdx.x;   // < 507904
    const float* src; int base, K;
    if (idx < 65536)       { src = W1; base = 0; K = 256; }
    else if (idx < 98304)  { src = W2; base = 65536; K = 128; }
    else if (idx < 262144) { int m = (idx - 98304) >> 15; src = W3 + m * HH * FF; base = 98304 + (m << 15); K = 128; }
    else if (idx < 425984) { int m = (idx - 262144) >> 15; src = W4 + m * HH * FF; base = 262144 + (m << 15); K = 128; }
    else                   { int m = (idx - 425984) >> 14; src = Wc + m * OUTD * FF; base = 425984 + (m << 14); K = 64; }
    int local = idx - base;
    int n = local / K, k = local - n * K;
    g_Wt[idx] = __float2bfloat16(src[k * 256 + n]);
}

// ---------------- column stats for x ----------------
__global__ void colstats_k(const float* __restrict__ X) {
    int col = threadIdx.x;
    int r0  = blockIdx.x * 128;
    float s = 0.f, s2 = 0.f;
#pragma unroll 8
    for (int r = 0; r < 128; r++) {
        float v = X[(r0 + r) * 256 + col];
        s += v; s2 += v * v;
    }
    atomicAdd(&g_sum[col], s);
    atomicAdd(&g_sumsq[col], s2);
}

// ---------------- input BN apply + trivial output (x4 vectorized) ----------
__global__ void apply_x_k(const float* __restrict__ x, const float* __restrict__ eg,
                          const float* __restrict__ eb, float* __restrict__ out, int out_size) {
    int idx4 = blockIdx.x * 256 + threadIdx.x;     // BB*FF/4 threads
    int col4 = (idx4 & 63) * 4, row = idx4 >> 6;
    float4 xv = *(const float4*)(x + (size_t)idx4 * 4);
    float v[4];
#pragma unroll
    for (int i = 0; i < 4; i++) {
        int col = col4 + i;
        float mean = g_sum[col] * (1.f / BB);
        float var  = g_sumsq[col] * (1.f / BB) - mean * mean;
        float a = eg[col] * rsqrtf(var + 1e-5f);
        float c = eb[col] - mean * a;
        v[i] = ((const float*)&xv)[i] * a + c;
    }
    *(float4*)(g_compl + (size_t)idx4 * 4) = make_float4(1.f, 1.f, 1.f, 1.f);
    __nv_bfloat162 p0 = {__float2bfloat16(v[0]), __float2bfloat16(v[1])};
    __nv_bfloat162 p1 = {__float2bfloat16(v[2]), __float2bfloat16(v[3])};
    *(__nv_bfloat162*)(g_xb + (size_t)idx4 * 4)     = p0;
    *(__nv_bfloat162*)(g_xb + (size_t)idx4 * 4 + 2) = p1;
    if (col4 < OUTD) {
        float4 o = make_float4(5.f * fmaxf(v[0], 0.f), 5.f * fmaxf(v[1], 0.f),
                               5.f * fmaxf(v[2], 0.f), 5.f * fmaxf(v[3], 0.f));
        *(float4*)(out + (size_t)row * OUTD + col4) = o;
    }
    if (idx4 == 0) for (int i = BB * OUTD; i < out_size; i++) out[i] = 0.0f;
}

// ---------------- bf16 HMMA GEMM (cp.async double-buffered) ------------
// g_Y[B,256] = A[B,K] @ W[K,256]
// asel: 0 = g_xb  1 = g_mb  2 = g_hb  3 = g_hb + 64 (fc)
// Fuses column sum / sumsq (fp32) into stage slice `st`.
__global__ __launch_bounds__(256, 2) void mma_k(int asel, int lda, int Woff, int K, int st) {
    extern __shared__ char smem[];
    __nv_bfloat16* sA = (__nv_bfloat16*)smem;                  // [2][128*BSTR]
    __nv_bfloat16* sB = (__nv_bfloat16*)(smem + 2 * 128 * BSTR * 2);

    const int tid = threadIdx.x, wid = tid >> 5, lane = tid & 31;
    const int row0 = blockIdx.y * 128, col0 = blockIdx.x * 128;

    const __nv_bfloat16* A =
        (asel == 0) ? g_xb :
        (asel == 1) ? g_mb :
        (asel == 2) ? g_hb : (g_hb + OUTD);
    const __nv_bfloat16* W = g_Wt + Woff;
    const int nch = K >> 6;

    float acc[2][8][4];
#pragma unroll
    for (int i = 0; i < 2; i++)
#pragma unroll
        for (int j = 0; j < 8; j++)
#pragma unroll
            for (int e = 0; e < 4; e++) acc[i][j][e] = 0.f;

    // cp.async coords: 4 rows-of-32 per thread per matrix, 16B each
    const int pr = tid >> 3, pc8 = (tid & 7) * 8;

    // ldmatrix coords
    const int a_row = (wid & 3) * 32 + (lane & 15);
    const int a_koff = (lane >> 4) << 3;
    const int b_row0 = (wid >> 2) * 64 + (lane & 7) + ((lane & 16) ? 8 : 0);
    const int b_koff = (lane & 8);

    // prefetch chunk 0
    {
#pragma unroll
        for (int t = 0; t < 4; t++) {
            int rr = pr + t * 32;
            cpasync16(smem_u32(&sA[rr * BSTR + pc8]), A + (size_t)(row0 + rr) * lda + pc8);
            cpasync16(smem_u32(&sB[rr * BSTR + pc8]), W + (size_t)(col0 + rr) * K + pc8);
        }
        asm volatile("cp.async.commit_group;");
    }

    for (int c = 0; c < nch; c++) {
        if (c + 1 < nch) {
            const int buf = (c + 1) & 1;
            const int k0 = (c + 1) * 64;
#pragma unroll
            for (int t = 0; t < 4; t++) {
                int rr = pr + t * 32;
                cpasync16(smem_u32(&sA[buf * 128 * BSTR + rr * BSTR + pc8]),
                          A + (size_t)(row0 + rr) * lda + k0 + pc8);
                cpasync16(smem_u32(&sB[buf * 128 * BSTR + rr * BSTR + pc8]),
                          W + (size_t)(col0 + rr) * K + k0 + pc8);
            }
            asm volatile("cp.async.commit_group;");
            asm volatile("cp.async.wait_group 1;");
        } else {
            asm volatile("cp.async.wait_group 0;");
        }
        __syncthreads();

        const __nv_bfloat16* abuf = &sA[(c & 1) * 128 * BSTR];
        const __nv_bfloat16* bbuf = &sB[(c & 1) * 128 * BSTR];
#pragma unroll
        for (int kk = 0; kk < 64; kk += 16) {
            uint32_t ah[2][4];
            ldsm4(ah[0], &abuf[a_row * BSTR + kk + a_koff]);
            ldsm4(ah[1], &abuf[(a_row + 16) * BSTR + kk + a_koff]);
#pragma unroll
            for (int nf2 = 0; nf2 < 4; nf2++) {
                uint32_t bh[4];
                ldsm4(bh, &bbuf[(b_row0 + nf2 * 16) * BSTR + kk + b_koff]);
                mma16816(acc[0][nf2 * 2],     ah[0], &bh[0]);
                mma16816(acc[0][nf2 * 2 + 1], ah[0], &bh[2]);
                mma16816(acc[1][nf2 * 2],     ah[1], &bh[0]);
                mma16816(acc[1][nf2 * 2 + 1], ah[1], &bh[2]);
            }
        }
        __syncthreads();
    }

    // ---- epilogue: write bf16 g_Y + fused fp32 column stats ----
    const int g = lane >> 2, tg = lane & 3;
    const int mbase = row0 + (wid & 3) * 32;
    const int nbase = col0 + (wid >> 2) * 64;
    float* S = g_sum   + st * 256;
    float* Q = g_sumsq + st * 256;

#pragma unroll
    for (int nf = 0; nf < 8; nf++) {
        int c = nbase + nf * 8 + tg * 2;
        float s0 = 0.f, s1 = 0.f, q0 = 0.f, q1 = 0.f;
#pragma unroll
        for (int mf = 0; mf < 2; mf++) {
            int r0 = mbase + mf * 16 + g;
            float e0 = acc[mf][nf][0], e1 = acc[mf][nf][1];
            float e2 = acc[mf][nf][2], e3 = acc[mf][nf][3];
            __nv_bfloat162 p0 = {__float2bfloat16(e0), __float2bfloat16(e1)};
            __nv_bfloat162 p1 = {__float2bfloat16(e2), __float2bfloat16(e3)};
            *(__nv_bfloat162*)(g_Y + (size_t)r0 * 256 + c)       = p0;
            *(__nv_bfloat162*)(g_Y + (size_t)(r0 + 8) * 256 + c) = p1;
            s0 += e0 + e2; s1 += e1 + e3;
            q0 += e0 * e0 + e2 * e2; q1 += e1 * e1 + e3 * e3;
        }
#pragma unroll
        for (int o = 4; o < 32; o <<= 1) {
            s0 += __shfl_xor_sync(0xffffffffu, s0, o);
            s1 += __shfl_xor_sync(0xffffffffu, s1, o);
            q0 += __shfl_xor_sync(0xffffffffu, q0, o);
            q1 += __shfl_xor_sync(0xffffffffu, q1, o);
        }
        int cl = c & 255;
        if (lane < 4) {
            atomicAdd(&S[cl], s0);
            atomicAdd(&S[cl + 1], s1);
            atomicAdd(&Q[cl], q0);
            atomicAdd(&Q[cl + 1], q1);
        }
    }
}

// ---------------- BN apply + GLU (+ residual), x2 vectorized ----------------
__global__ void act_glu_k(const float* __restrict__ g, const float* __restrict__ b,
                          int st, int residual) {
    int idx2 = blockIdx.x * 256 + threadIdx.x;   // BB*HH/2 threads
    int j2 = (idx2 & 63) * 2, row = idx2 >> 6;
    const float* S = g_sum   + st * 256;
    const float* Q = g_sumsq + st * 256;

    __nv_bfloat162 y1p = *(const __nv_bfloat162*)(g_Y + (size_t)row * 256 + j2);
    __nv_bfloat162 y2p = *(const __nv_bfloat162*)(g_Y + (size_t)row * 256 + 128 + j2);
    float vout[2];
#pragma unroll
    for (int i = 0; i < 2; i++) {
        int j = j2 + i;
        float m1 = S[j]       * (1.f / BB), m2 = S[j + 128] * (1.f / BB);
        float v1 = Q[j]       * (1.f / BB) - m1 * m1;
        float v2 = Q[j + 128] * (1.f / BB) - m2 * m2;
        float a1 = g[j]       * rsqrtf(v1 + 1e-5f);
        float a2 = g[j + 128] * rsqrtf(v2 + 1e-5f);
        float c1 = b[j]       - m1 * a1;
        float c2 = b[j + 128] - m2 * a2;
        float y1 = __bfloat162float((i == 0) ? y1p.x : y1p.y) * a1 + c1;
        float y2 = __bfloat162float((i == 0) ? y2p.x : y2p.y) * a2 + c2;
        vout[i] = y1 / (1.0f + expf(-y2));
    }
    if (residual) {
        float2 hp = *(const float2*)(g_h + (size_t)idx2 * 2);
        vout[0] = (vout[0] + hp.x) * 0.70710678118654752f;
        vout[1] = (vout[1] + hp.y) * 0.70710678118654752f;
    }
    *(float2*)(g_h + (size_t)idx2 * 2) = make_float2(vout[0], vout[1]);
    __nv_bfloat162 hb = {__float2bfloat16(vout[0]), __float2bfloat16(vout[1])};
    *(__nv_bfloat162*)(g_hb + (size_t)idx2 * 2) = hb;
}

// ---------------- softmax / entropy / mask update ----------------
__global__ void mask_k(const float* __restrict__ gcv, const float* __restrict__ bcv,
                       int st, int update, float* __restrict__ ent_out) {
    int lane = threadIdx.x & 31, w = threadIdx.x >> 5;
    int row  = blockIdx.x * 8 + w;
    int base = row * 256;
    const float* S = g_sum   + st * 256;
    const float* Q = g_sumsq + st * 256;

    float t[8], cm[8];
    float mx = -1e30f;
#pragma unroll
    for (int k = 0; k < 8; k++) {
        int col = lane + 32 * k;
        float mean = S[col] * (1.f / BB);
        float var  = Q[col] * (1.f / BB) - mean * mean;
        float a = gcv[col] * rsqrtf(var + 1e-5f);
        float c = bcv[col] - mean * a;
        cm[k] = g_compl[base + col];
        t[k]  = (__bfloat162float(g_Y[base + col]) * a + c) * cm[k];
        mx = fmaxf(mx, t[k]);
    }
#pragma unroll
    for (int o = 16; o; o >>= 1) mx = fmaxf(mx, __shfl_xor_sync(0xffffffffu, mx, o));

    float e[8], ss = 0.f;
#pragma unroll
    for (int k = 0; k < 8; k++) { e[k] = expf(t[k] - mx); ss += e[k]; }
#pragma unroll
    for (int o = 16; o; o >>= 1) ss += __shfl_xor_sync(0xffffffffu, ss, o);

    float inv = 1.0f / ss;
    float ent = 0.f;
#pragma unroll
    for (int k = 0; k < 8; k++) {
        float m = e[k] * inv;
        ent -= m * logf(m + 1e-5f);
        if (update) {
            int col = lane + 32 * k;
            g_compl[base + col] = cm[k] * (1.5f - m);
            g_mb[base + col] = __float2bfloat16(m * __bfloat162float(g_xb[base + col]));
        }
    }
#pragma unroll
    for (int o = 16; o; o >>= 1) ent += __shfl_xor_sync(0xffffffffu, ent, o);

    __shared__ float se[8];
    if (lane == 0) se[w] = ent;
    __syncthreads();
    if (threadIdx.x == 0) {
        float tot = 0.f;
#pragma unroll
        for (int i = 0; i < 8; i++) tot += se[i];
        atomicAdd(ent_out, tot * (1.0f / (32768.0f * 5.0f)));
    }
}

// ---------------- launcher ----------------
extern "C" void kernel_launch(void* const* d_in, const int* in_sizes, int n_in,
                              void* d_out, int out_size) {
    (void)in_sizes; (void)n_in;
    const float* x     = (const float*)d_in[0];
    const float* enc_g = (const float*)d_in[1];
    const float* enc_b = (const float*)d_in[2];
    const float* W1    = (const float*)d_in[3];
    const float* g1    = (const float*)d_in[4];
    const float* b1    = (const float*)d_in[5];
    const float* W2    = (const float*)d_in[6];
    const float* g2    = (const float*)d_in[7];
    const float* b2    = (const float*)d_in[8];
    const float* W3    = (const float*)d_in[9];
    const float* g3    = (const float*)d_in[10];
    const float* b3    = (const float*)d_in[11];
    const float* W4    = (const float*)d_in[12];
    const float* g4    = (const float*)d_in[13];
    const float* b4    = (const float*)d_in[14];
    const float* Wc    = (const float*)d_in[15];
    const float* gc    = (const float*)d_in[16];
    const float* bc    = (const float*)d_in[17];

    float* out = (float*)d_out;
    float* ent = out + (out_size - 1);

    const int SMEMSZ = 4 * 128 * BSTR * 2;   // 73728: 2-stage A + 2-stage B
    static int smem_set = 0;
    if (!smem_set) {
        cudaFuncSetAttribute(mma_k, cudaFuncAttributeMaxDynamicSharedMemorySize, SMEMSZ);
        smem_set = 1;
    }

    dim3 ggrid(2, 256);

    // setup
    zero_stats_k<<<NSTG, 256>>>();
    convw_k<<<1984, 256>>>(W1, W2, W3, W4, Wc);
    colstats_k<<<256, 256>>>(x);
    apply_x_k<<<BB * FF / 1024, 256>>>(x, enc_g, enc_b, out, out_size);

    // steps 0..4 (step 5 is dead code: out depends only on BN(x))
    for (int ni = 0; ni < 5; ni++) {
        int st = 1 + ni * 5;
        // G1: [B,256] @ W1
        mma_k<<<ggrid, 256, SMEMSZ>>>((ni == 0) ? 0 : 1, 256, 0, 256, st);
        act_glu_k<<<BB * HH / 512, 256>>>(g1, b1, st, 0);
        // G2 (+res)
        mma_k<<<ggrid, 256, SMEMSZ>>>(2, 128, 65536, 128, st + 1);
        act_glu_k<<<BB * HH / 512, 256>>>(g2, b2, st + 1, 1);
        // G3 (+res)
        mma_k<<<ggrid, 256, SMEMSZ>>>(2, 128, 98304 + ni * 32768, 128, st + 2);
        act_glu_k<<<BB * HH / 512, 256>>>(g3 + ni * 256, b3 + ni * 256, st + 2, 1);
        // G4 (+res)
        mma_k<<<ggrid, 256, SMEMSZ>>>(2, 128, 262144 + ni * 32768, 128, st + 3);
        act_glu_k<<<BB * HH / 512, 256>>>(g4 + ni * 256, b4 + ni * 256, st + 3, 1);
        // Gc: fc = h[:,64:128] @ Wc[ni]
        mma_k<<<ggrid, 256, SMEMSZ>>>(3, 128, 425984 + ni * 16384, 64, st + 4);
        // softmax / entropy / mask update
        mask_k<<<BB / 8, 256>>>(gc + ni * 256, bc + ni * 256, st + 4, (ni < 4) ? 1 : 0, ent);
    }
}

// round 10
// speedup vs baseline: 1.4716x; 1.0296x over previous
#include <cuda_runtime.h>
#include <cuda_fp16.h>
#include <math.h>
#include <stdint.h>

#define BB   32768
#define FF   256
#define HH   128
#define OUTD 64
#define NSTG 26
#define BSTR 72    // fp16 elems per smem row: 128B data + 16B pad, conflict-free

// ---------------- device scratch ----------------
__device__ __half g_compl[BB * FF];          // fp16 prior/complement
__device__ __half g_Y[BB * FF];              // GEMM output (fp16; stats in fp32)
__device__ __half g_hh[BB * HH];             // fp16 activation + residual carrier
__device__ __half g_xh[BB * FF];             // fp16 BN(x)
__device__ __half g_mh[BB * FF];             // fp16 masked
__device__ __half g_Wt[507904];              // transposed weights [N=256, K]
__device__ float g_sum[NSTG * 256];
__device__ float g_sumsq[NSTG * 256];

// ---------------- helpers ----------------
__device__ __forceinline__ uint32_t smem_u32(const void* p) {
    return (uint32_t)__cvta_generic_to_shared(p);
}
__device__ __forceinline__ void ldsm4(uint32_t* r, const void* p) {
    asm volatile("ldmatrix.sync.aligned.m8n8.x4.shared.b16 {%0,%1,%2,%3}, [%4];"
                 : "=r"(r[0]), "=r"(r[1]), "=r"(r[2]), "=r"(r[3]) : "r"(smem_u32(p)));
}
__device__ __forceinline__ void mma16816(float* c, const uint32_t* a, const uint32_t* b) {
    asm volatile(
        "mma.sync.aligned.m16n8k16.row.col.f32.f16.f16.f32 "
        "{%0,%1,%2,%3}, {%4,%5,%6,%7}, {%8,%9}, {%0,%1,%2,%3};"
        : "+f"(c[0]), "+f"(c[1]), "+f"(c[2]), "+f"(c[3])
        : "r"(a[0]), "r"(a[1]), "r"(a[2]), "r"(a[3]), "r"(b[0]), "r"(b[1]));
}
__device__ __forceinline__ void cpasync16(uint32_t dst, const void* src) {
    asm volatile("cp.async.ca.shared.global [%0], [%1], 16;" :: "r"(dst), "l"(src));
}

// ---------------- stats zero ----------------
__global__ void zero_stats_k() {
    int i = blockIdx.x * 256 + threadIdx.x;
    g_sum[i] = 0.f; g_sumsq[i] = 0.f;
}

// ---------------- W transpose -> fp16 [N=256,K] ----------------
__global__ void convw_k(const float* __restrict__ W1, const float* __restrict__ W2,
                        const float* __restrict__ W3, const float* __restrict__ W4,
                        const float* __restrict__ Wc) {
    int idx = blockIdx.x * 256 + threadIdx.x;   // < 507904
    const float* src; int base, K;
    if (idx < 65536)       { src = W1; base = 0; K = 256; }
    else if (idx < 98304)  { src = W2; base = 65536; K = 128; }
    else if (idx < 262144) { int m = (idx - 98304) >> 15; src = W3 + m * HH * FF; base = 98304 + (m << 15); K = 128; }
    else if (idx < 425984) { int m = (idx - 262144) >> 15; src = W4 + m * HH * FF; base = 262144 + (m << 15); K = 128; }
    else                   { int m = (idx - 425984) >> 14; src = Wc + m * OUTD * FF; base = 425984 + (m << 14); K = 64; }
    int local = idx - base;
    int n = local / K, k = local - n * K;
    g_Wt[idx] = __float2half(src[k * 256 + n]);
}

// ---------------- column stats for x ----------------
__global__ void colstats_k(const float* __restrict__ X) {
    int col = threadIdx.x;
    int r0  = blockIdx.x * 128;
    float s = 0.f, s2 = 0.f;
#pragma unroll 8
    for (int r = 0; r < 128; r++) {
        float v = X[(r0 + r) * 256 + col];
        s += v; s2 += v * v;
    }
    atomicAdd(&g_sum[col], s);
    atomicAdd(&g_sumsq[col], s2);
}

// ---------------- input BN apply + trivial output (x4 vectorized) ----------
__global__ void apply_x_k(const float* __restrict__ x, const float* __restrict__ eg,
                          const float* __restrict__ eb, float* __restrict__ out, int out_size) {
    int idx4 = blockIdx.x * 256 + threadIdx.x;     // BB*FF/4 threads
    int col4 = (idx4 & 63) * 4, row = idx4 >> 6;
    float4 xv = *(const float4*)(x + (size_t)idx4 * 4);
    float v[4];
#pragma unroll
    for (int i = 0; i < 4; i++) {
        int col = col4 + i;
        float mean = g_sum[col] * (1.f / BB);
        float var  = g_sumsq[col] * (1.f / BB) - mean * mean;
        float a = eg[col] * rsqrtf(var + 1e-5f);
        float c = eb[col] - mean * a;
        v[i] = ((const float*)&xv)[i] * a + c;
    }
    __half2 one2 = __floats2half2_rn(1.f, 1.f);
    *(__half2*)(g_compl + (size_t)idx4 * 4)     = one2;
    *(__half2*)(g_compl + (size_t)idx4 * 4 + 2) = one2;
    __half2 p0 = __floats2half2_rn(v[0], v[1]);
    __half2 p1 = __floats2half2_rn(v[2], v[3]);
    *(__half2*)(g_xh + (size_t)idx4 * 4)     = p0;
    *(__half2*)(g_xh + (size_t)idx4 * 4 + 2) = p1;
    if (col4 < OUTD) {
        float4 o = make_float4(5.f * fmaxf(v[0], 0.f), 5.f * fmaxf(v[1], 0.f),
                               5.f * fmaxf(v[2], 0.f), 5.f * fmaxf(v[3], 0.f));
        *(float4*)(out + (size_t)row * OUTD + col4) = o;
    }
    if (idx4 == 0) for (int i = BB * OUTD; i < out_size; i++) out[i] = 0.0f;
}

// ---------------- fp16 HMMA GEMM (cp.async double-buffered) ------------
// g_Y[B,256] = A[B,K] @ W[K,256]
// asel: 0 = g_xh  1 = g_mh  2 = g_hh  3 = g_hh + 64 (fc)
// Fuses column sum / sumsq (fp32) into stage slice `st`.
__global__ __launch_bounds__(256, 2) void mma_k(int asel, int lda, int Woff, int K, int st) {
    extern __shared__ char smem[];
    __half* sA = (__half*)smem;                  // [2][128*BSTR]
    __half* sB = (__half*)(smem + 2 * 128 * BSTR * 2);

    const int tid = threadIdx.x, wid = tid >> 5, lane = tid & 31;
    const int row0 = blockIdx.y * 128, col0 = blockIdx.x * 128;

    const __half* A =
        (asel == 0) ? g_xh :
        (asel == 1) ? g_mh :
        (asel == 2) ? g_hh : (g_hh + OUTD);
    const __half* W = g_Wt + Woff;
    const int nch = K >> 6;

    float acc[2][8][4];
#pragma unroll
    for (int i = 0; i < 2; i++)
#pragma unroll
        for (int j = 0; j < 8; j++)
#pragma unroll
            for (int e = 0; e < 4; e++) acc[i][j][e] = 0.f;

    // cp.async coords: 4 rows-of-32 per thread per matrix, 16B each
    const int pr = tid >> 3, pc8 = (tid & 7) * 8;

    // ldmatrix coords
    const int a_row = (wid & 3) * 32 + (lane & 15);
    const int a_koff = (lane >> 4) << 3;
    const int b_row0 = (wid >> 2) * 64 + (lane & 7) + ((lane & 16) ? 8 : 0);
    const int b_koff = (lane & 8);

    // prefetch chunk 0
    {
#pragma unroll
        for (int t = 0; t < 4; t++) {
            int rr = pr + t * 32;
            cpasync16(smem_u32(&sA[rr * BSTR + pc8]), A + (size_t)(row0 + rr) * lda + pc8);
            cpasync16(smem_u32(&sB[rr * BSTR + pc8]), W + (size_t)(col0 + rr) * K + pc8);
        }
        asm volatile("cp.async.commit_group;");
    }

    for (int c = 0; c < nch; c++) {
        if (c + 1 < nch) {
            const int buf = (c + 1) & 1;
            const int k0 = (c + 1) * 64;
#pragma unroll
            for (int t = 0; t < 4; t++) {
                int rr = pr + t * 32;
                cpasync16(smem_u32(&sA[buf * 128 * BSTR + rr * BSTR + pc8]),
                          A + (size_t)(row0 + rr) * lda + k0 + pc8);
                cpasync16(smem_u32(&sB[buf * 128 * BSTR + rr * BSTR + pc8]),
                          W + (size_t)(col0 + rr) * K + k0 + pc8);
            }
            asm volatile("cp.async.commit_group;");
            asm volatile("cp.async.wait_group 1;");
        } else {
            asm volatile("cp.async.wait_group 0;");
        }
        __syncthreads();

        const __half* abuf = &sA[(c & 1) * 128 * BSTR];
        const __half* bbuf = &sB[(c & 1) * 128 * BSTR];
#pragma unroll
        for (int kk = 0; kk < 64; kk += 16) {
            uint32_t ah[2][4];
            ldsm4(ah[0], &abuf[a_row * BSTR + kk + a_koff]);
            ldsm4(ah[1], &abuf[(a_row + 16) * BSTR + kk + a_koff]);
#pragma unroll
            for (int nf2 = 0; nf2 < 4; nf2++) {
                uint32_t bh[4];
                ldsm4(bh, &bbuf[(b_row0 + nf2 * 16) * BSTR + kk + b_koff]);
                mma16816(acc[0][nf2 * 2],     ah[0], &bh[0]);
                mma16816(acc[0][nf2 * 2 + 1], ah[0], &bh[2]);
                mma16816(acc[1][nf2 * 2],     ah[1], &bh[0]);
                mma16816(acc[1][nf2 * 2 + 1], ah[1], &bh[2]);
            }
        }
        __syncthreads();
    }

    // ---- epilogue: write fp16 g_Y + fused fp32 column stats ----
    const int g = lane >> 2, tg = lane & 3;
    const int mbase = row0 + (wid & 3) * 32;
    const int nbase = col0 + (wid >> 2) * 64;
    float* S = g_sum   + st * 256;
    float* Q = g_sumsq + st * 256;

#pragma unroll
    for (int nf = 0; nf < 8; nf++) {
        int c = nbase + nf * 8 + tg * 2;
        float s0 = 0.f, s1 = 0.f, q0 = 0.f, q1 = 0.f;
#pragma unroll
        for (int mf = 0; mf < 2; mf++) {
            int r0 = mbase + mf * 16 + g;
            float e0 = acc[mf][nf][0], e1 = acc[mf][nf][1];
            float e2 = acc[mf][nf][2], e3 = acc[mf][nf][3];
            *(__half2*)(g_Y + (size_t)r0 * 256 + c)       = __floats2half2_rn(e0, e1);
            *(__half2*)(g_Y + (size_t)(r0 + 8) * 256 + c) = __floats2half2_rn(e2, e3);
            s0 += e0 + e2; s1 += e1 + e3;
            q0 += e0 * e0 + e2 * e2; q1 += e1 * e1 + e3 * e3;
        }
#pragma unroll
        for (int o = 4; o < 32; o <<= 1) {
            s0 += __shfl_xor_sync(0xffffffffu, s0, o);
            s1 += __shfl_xor_sync(0xffffffffu, s1, o);
            q0 += __shfl_xor_sync(0xffffffffu, q0, o);
            q1 += __shfl_xor_sync(0xffffffffu, q1, o);
        }
        int cl = c & 255;
        if (lane < 4) {
            atomicAdd(&S[cl], s0);
            atomicAdd(&S[cl + 1], s1);
            atomicAdd(&Q[cl], q0);
            atomicAdd(&Q[cl + 1], q1);
        }
    }
}

// ---------------- BN apply + GLU (+ residual), x2 vectorized ----------------
__global__ void act_glu_k(const float* __restrict__ g, const float* __restrict__ b,
                          int st, int residual) {
    int idx2 = blockIdx.x * 256 + threadIdx.x;   // BB*HH/2 threads
    int j2 = (idx2 & 63) * 2, row = idx2 >> 6;
    const float* S = g_sum   + st * 256;
    const float* Q = g_sumsq + st * 256;

    __half2 y1p = *(const __half2*)(g_Y + (size_t)row * 256 + j2);
    __half2 y2p = *(const __half2*)(g_Y + (size_t)row * 256 + 128 + j2);
    float vout[2];
#pragma unroll
    for (int i = 0; i < 2; i++) {
        int j = j2 + i;
        float m1 = S[j]       * (1.f / BB), m2 = S[j + 128] * (1.f / BB);
        float v1 = Q[j]       * (1.f / BB) - m1 * m1;
        float v2 = Q[j + 128] * (1.f / BB) - m2 * m2;
        float a1 = g[j]       * rsqrtf(v1 + 1e-5f);
        float a2 = g[j + 128] * rsqrtf(v2 + 1e-5f);
        float c1 = b[j]       - m1 * a1;
        float c2 = b[j + 128] - m2 * a2;
        float y1 = __half2float((i == 0) ? y1p.x : y1p.y) * a1 + c1;
        float y2 = __half2float((i == 0) ? y2p.x : y2p.y) * a2 + c2;
        vout[i] = y1 / (1.0f + expf(-y2));
    }
    if (residual) {
        __half2 hp = *(const __half2*)(g_hh + (size_t)idx2 * 2);
        vout[0] = (vout[0] + __half2float(hp.x)) * 0.70710678118654752f;
        vout[1] = (vout[1] + __half2float(hp.y)) * 0.70710678118654752f;
    }
    *(__half2*)(g_hh + (size_t)idx2 * 2) = __floats2half2_rn(vout[0], vout[1]);
}

// ---------------- softmax / entropy / mask update ----------------
__global__ void mask_k(const float* __restrict__ gcv, const float* __restrict__ bcv,
                       int st, int update, float* __restrict__ ent_out) {
    int lane = threadIdx.x & 31, w = threadIdx.x >> 5;
    int row  = blockIdx.x * 8 + w;
    int base = row * 256;
    const float* S = g_sum   + st * 256;
    const float* Q = g_sumsq + st * 256;

    float t[8], cm[8];
    float mx = -1e30f;
#pragma unroll
    for (int k = 0; k < 8; k++) {
        int col = lane + 32 * k;
        float mean = S[col] * (1.f / BB);
        float var  = Q[col] * (1.f / BB) - mean * mean;
        float a = gcv[col] * rsqrtf(var + 1e-5f);
        float c = bcv[col] - mean * a;
        cm[k] = __half2float(g_compl[base + col]);
        t[k]  = (__half2float(g_Y[base + col]) * a + c) * cm[k];
        mx = fmaxf(mx, t[k]);
    }
#pragma unroll
    for (int o = 16; o; o >>= 1) mx = fmaxf(mx, __shfl_xor_sync(0xffffffffu, mx, o));

    float e[8], ss = 0.f;
#pragma unroll
    for (int k = 0; k < 8; k++) { e[k] = expf(t[k] - mx); ss += e[k]; }
#pragma unroll
    for (int o = 16; o; o >>= 1) ss += __shfl_xor_sync(0xffffffffu, ss, o);

    float inv = 1.0f / ss;
    float ent = 0.f;
#pragma unroll
    for (int k = 0; k < 8; k++) {
        float m = e[k] * inv;
        ent -= m * logf(m + 1e-5f);
        if (update) {
            int col = lane + 32 * k;
            g_compl[base + col] = __float2half(cm[k] * (1.5f - m));
            g_mh[base + col] = __float2half(m * __half2float(g_xh[base + col]));
        }
    }
#pragma unroll
    for (int o = 16; o; o >>= 1) ent += __shfl_xor_sync(0xffffffffu, ent, o);

    __shared__ float se[8];
    if (lane == 0) se[w] = ent;
    __syncthreads();
    if (threadIdx.x == 0) {
        float tot = 0.f;
#pragma unroll
        for (int i = 0; i < 8; i++) tot += se[i];
        atomicAdd(ent_out, tot * (1.0f / (32768.0f * 5.0f)));
    }
}

// ---------------- launcher ----------------
extern "C" void kernel_launch(void* const* d_in, const int* in_sizes, int n_in,
                              void* d_out, int out_size) {
    (void)in_sizes; (void)n_in;
    const float* x     = (const float*)d_in[0];
    const float* enc_g = (const float*)d_in[1];
    const float* enc_b = (const float*)d_in[2];
    const float* W1    = (const float*)d_in[3];
    const float* g1    = (const float*)d_in[4];
    const float* b1    = (const float*)d_in[5];
    const float* W2    = (const float*)d_in[6];
    const float* g2    = (const float*)d_in[7];
    const float* b2    = (const float*)d_in[8];
    const float* W3    = (const float*)d_in[9];
    const float* g3    = (const float*)d_in[10];
    const float* b3    = (const float*)d_in[11];
    const float* W4    = (const float*)d_in[12];
    const float* g4    = (const float*)d_in[13];
    const float* b4    = (const float*)d_in[14];
    const float* Wc    = (const float*)d_in[15];
    const float* gc    = (const float*)d_in[16];
    const float* bc    = (const float*)d_in[17];

    float* out = (float*)d_out;
    float* ent = out + (out_size - 1);

    const int SMEMSZ = 4 * 128 * BSTR * 2;   // 73728: 2-stage A + 2-stage B
    cudaFuncSetAttribute(mma_k, cudaFuncAttributeMaxDynamicSharedMemorySize, SMEMSZ);

    dim3 ggrid(2, 256);

    // setup
    zero_stats_k<<<NSTG, 256>>>();
    convw_k<<<1984, 256>>>(W1, W2, W3, W4, Wc);
    colstats_k<<<256, 256>>>(x);
    apply_x_k<<<BB * FF / 1024, 256>>>(x, enc_g, enc_b, out, out_size);

    // steps 0..4 (step 5 is dead code: out depends only on BN(x))
    for (int ni = 0; ni < 5; ni++) {
        int st = 1 + ni * 5;
        // G1: [B,256] @ W1
        mma_k<<<ggrid, 256, SMEMSZ>>>((ni == 0) ? 0 : 1, 256, 0, 256, st);
        act_glu_k<<<BB * HH / 512, 256>>>(g1, b1, st, 0);
        // G2 (+res)
        mma_k<<<ggrid, 256, SMEMSZ>>>(2, 128, 65536, 128, st + 1);
        act_glu_k<<<BB * HH / 512, 256>>>(g2, b2, st + 1, 1);
        // G3 (+res)
        mma_k<<<ggrid, 256, SMEMSZ>>>(2, 128, 98304 + ni * 32768, 128, st + 2);
        act_glu_k<<<BB * HH / 512, 256>>>(g3 + ni * 256, b3 + ni * 256, st + 2, 1);
        // G4 (+res)
        mma_k<<<ggrid, 256, SMEMSZ>>>(2, 128, 262144 + ni * 32768, 128, st + 3);
        act_glu_k<<<BB * HH / 512, 256>>>(g4 + ni * 256, b4 + ni * 256, st + 3, 1);
        // Gc: fc = h[:,64:128] @ Wc[ni]
        mma_k<<<ggrid, 256, SMEMSZ>>>(3, 128, 425984 + ni * 16384, 64, st + 4);
        // softmax / entropy / mask update
        mask_k<<<BB / 8, 256>>>(gc + ni * 256, bc + ni * 256, st + 4, (ni < 4) ? 1 : 0, ent);
    }
}